// round 6
// baseline (speedup 1.0000x reference)
#include <cuda_runtime.h>

typedef unsigned long long u64;

#define HALF     512
#define BATCH    8192
#define DEPTH    20
#define TB       8           // batch columns per block (4 bp threads x 2 cols)
#define NTHREADS 128         // 32 row-threads x 4 batch-pair threads
#define NBLOCKS  (BATCH / TB)

// Scalar (c, s) coefficients, 8B each. P1-type layers (l%10 < 5) stored
// PERMUTED: natural pair index p -> slot (p&15)*32 + (p>>4), so BOTH pass
// types address coefs as m*32 + rt.
__device__ float2 g_cs[DEPTH * HALF];

__global__ void sincos_kernel(const float* __restrict__ ang) {
    int i = blockIdx.x * blockDim.x + threadIdx.x;
    if (i < DEPTH * HALF) {
        const int l = i / HALF;
        const int p = i % HALF;
        float s, c;
        sincosf(ang[i], &s, &c);
        const int slot = ((l % 10) < 5) ? ((p & 15) * 32 + (p >> 4)) : p;
        g_cs[l * HALF + slot] = make_float2(c, s);
    }
}

// ---- packed f32x2 helpers (sm_100) ----
__device__ __forceinline__ u64 pk2(float v) {
    u64 r; asm("mov.b64 %0, {%1, %1};" : "=l"(r) : "f"(v)); return r;
}
__device__ __forceinline__ u64 mul2(u64 a, u64 b) {
    u64 d; asm("mul.rn.f32x2 %0, %1, %2;" : "=l"(d) : "l"(a), "l"(b)); return d;
}
__device__ __forceinline__ u64 fma2(u64 a, u64 b, u64 c) {
    u64 d; asm("fma.rn.f32x2 %0, %1, %2, %3;" : "=l"(d) : "l"(a), "l"(b), "l"(c)); return d;
}

// Givens rotation: y0 = c*x0 + s*x1 ; y1 = -s*x0 + c*x1 (2 packed batches)
__device__ __forceinline__ void rot(u64& x0, u64& x1, u64 cc, u64 ss, u64 ns) {
    const u64 y0 = fma2(cc, x0, mul2(ss, x1));
    const u64 y1 = fma2(ns, x0, mul2(cc, x1));
    x0 = y0; x1 = y1;
}

// Five butterfly levels fully in registers, flattened into 20 q-steps with a
// software-pipelined coefficient stream: step u's rotations overlap step u+1's
// 4 coefficient loads. Coef slot = m*32 + rt; pairs (j, j+2^l),
// j = ((m>>l)<<(l+1)) | (m & (2^l - 1)).
__device__ __forceinline__ void pass5(u64* Xv, const float2* __restrict__ lt) {
    float2 cf[4];
#pragma unroll
    for (int t = 0; t < 4; ++t) cf[t] = __ldg(lt + t * 32);

#pragma unroll
    for (int u = 0; u < 20; ++u) {
        const int l = u >> 2;
        const int q = u & 3;
        float2 nf[4];
        if (u < 19) {
            const int l2 = (u + 1) >> 2;
            const int q2 = (u + 1) & 3;
#pragma unroll
            for (int t = 0; t < 4; ++t)
                nf[t] = __ldg(lt + l2 * HALF + (q2 * 4 + t) * 32);
        }
#pragma unroll
        for (int t = 0; t < 4; ++t) {
            const int m  = q * 4 + t;
            const int sg = 1 << l;
            const int j  = ((m >> l) << (l + 1)) | (m & (sg - 1));
            const u64 cc = pk2(cf[t].x);
            const u64 ss = pk2(cf[t].y);
            const u64 ns = ss ^ 0x8000000080000000ULL;
            rot(Xv[j], Xv[j + sg], cc, ss, ns);
        }
#pragma unroll
        for (int t = 0; t < 4; ++t) cf[t] = nf[t];
    }
}

// Smem swizzle (u64 units): addr(row,bp) = (row<<2 | bp) ^ (((row>>5)&3)<<2).
// Warp = 8 consecutive rt x 4 bp. Bank-pair (addr&15):
//   layout A (row=rt*32+j): ((j^rt)&3)<<2 | bp  -> rt spans 8 -> 16 bank-pairs x2 lanes
//   layout B (row=rt+32j):  ((rt^j)&3)<<2 | bp  -> rt spans 8 -> 16 bank-pairs x2 lanes
// Optimal 2-phase 256B accesses in both directions; bijective.
#define ADRA(j) (baseA + ((((j) & 3) ^ eA) << 2) + (((j) >> 2) << 4))  // row = rt*32+j
#define ADRB(j) ((j) * 128 + baseB + ((((j) & 3) ^ eA) << 2))          // row = rt+32j

extern "C" __global__ void __launch_bounds__(NTHREADS, 5)
butterfly_kernel(const float* __restrict__ X, float* __restrict__ Y)
{
    extern __shared__ u64 tile[];          // 1024 rows x 4 bp x 8B = 32 KB

    const int bp = threadIdx.x & 3;        // batch-pair (2 cols) 0..3
    const int rt = threadIdx.x >> 2;       // row-thread 0..31
    const long long bb = (long long)blockIdx.x * TB + bp * 2;

    const int eA    = rt & 3;
    const int baseA = rt * 128 + bp;
    const int baseB = (rt & ~3) * 4 + bp;

    u64 Xa[32];                            // 32 rows x 2 batch columns

    // Load, layout A: reg j = row rt*32+j
#pragma unroll
    for (int j = 0; j < 32; ++j)
        Xa[j] = *reinterpret_cast<const u64*>(X + (long long)(rt * 32 + j) * BATCH + bb);

    const float2* lt = g_cs + rt;

#pragma unroll 1
    for (int sp = 0; sp < 2; ++sp) {
        // layers sp*10 .. sp*10+4 (register strides 1..16 in layout A)
        pass5(Xa, lt + (sp * 10) * HALF);

        // exchange A -> B
        __syncthreads();
#pragma unroll
        for (int j = 0; j < 32; ++j) tile[ADRA(j)] = Xa[j];
        __syncthreads();
#pragma unroll
        for (int j = 0; j < 32; ++j) Xa[j] = tile[ADRB(j)];

        // layers sp*10+5 .. sp*10+9 (strides 32..512 in layout B)
        pass5(Xa, lt + (sp * 10 + 5) * HALF);

        if (sp == 0) {
            // exchange B -> A
            __syncthreads();
#pragma unroll
            for (int j = 0; j < 32; ++j) tile[ADRB(j)] = Xa[j];
            __syncthreads();
#pragma unroll
            for (int j = 0; j < 32; ++j) Xa[j] = tile[ADRA(j)];
        }
    }

    // Store, layout B: reg j = row rt+32j
#pragma unroll
    for (int j = 0; j < 32; ++j)
        *reinterpret_cast<u64*>(Y + (long long)(rt + 32 * j) * BATCH + bb) = Xa[j];
}

extern "C" void kernel_launch(void* const* d_in, const int* in_sizes, int n_in,
                              void* d_out, int out_size)
{
    const float* X = (const float*)d_in[0];
    const float* A = (const float*)d_in[1];
    if (n_in >= 2 && in_sizes[0] < in_sizes[1]) {   // defensive: X is the big one
        const float* t = X; X = A; A = t;
    }
    float* Y = (float*)d_out;

    cudaFuncSetAttribute(butterfly_kernel,
                         cudaFuncAttributeMaxDynamicSharedMemorySize, 32768);

    sincos_kernel<<<(DEPTH * HALF + 255) / 256, 256>>>(A);
    butterfly_kernel<<<NBLOCKS, NTHREADS, 32768>>>(X, Y);
}

// round 7
// speedup vs baseline: 1.0370x; 1.0370x over previous
#include <cuda_runtime.h>

typedef unsigned long long u64;

#define HALF     512
#define BATCH    8192
#define DEPTH    20
#define TB       8           // batch columns per block (4 bp threads x 2 cols)
#define NTHREADS 128         // 32 row-threads x 4 batch-pair threads
#define NBLOCKS  (BATCH / TB)

// Scalar (c, s) coefficients, 8B each (80 KB total -> fits in L1 once smem <= 148KB).
// P1-type layers (l%10 < 5) stored PERMUTED: pair p -> slot (p&15)*32 + (p>>4),
// so BOTH pass types address coefs as m*32 + rt.
__device__ float2 g_cs[DEPTH * HALF];

__global__ void sincos_kernel(const float* __restrict__ ang) {
    int i = blockIdx.x * blockDim.x + threadIdx.x;
    if (i < DEPTH * HALF) {
        const int l = i / HALF;
        const int p = i % HALF;
        float s, c;
        sincosf(ang[i], &s, &c);
        const int slot = ((l % 10) < 5) ? ((p & 15) * 32 + (p >> 4)) : p;
        g_cs[l * HALF + slot] = make_float2(c, s);
    }
}

// ---- packed f32x2 helpers (sm_100) ----
__device__ __forceinline__ u64 pk2(float v) {
    u64 r; asm("mov.b64 %0, {%1, %1};" : "=l"(r) : "f"(v)); return r;
}
__device__ __forceinline__ u64 mul2(u64 a, u64 b) {
    u64 d; asm("mul.rn.f32x2 %0, %1, %2;" : "=l"(d) : "l"(a), "l"(b)); return d;
}
__device__ __forceinline__ u64 fma2(u64 a, u64 b, u64 c) {
    u64 d; asm("fma.rn.f32x2 %0, %1, %2, %3;" : "=l"(d) : "l"(a), "l"(b), "l"(c)); return d;
}

// Givens rotation: y0 = c*x0 + s*x1 ; y1 = -s*x0 + c*x1 (2 packed batches)
__device__ __forceinline__ void rot(u64& x0, u64& x1, u64 cc, u64 ss, u64 ns) {
    const u64 y0 = fma2(cc, x0, mul2(ss, x1));
    const u64 y1 = fma2(ns, x0, mul2(cc, x1));
    x0 = y0; x1 = y1;
}

// Five butterfly levels fully in registers, flattened into 20 q-steps with a
// dist-1 pipelined coefficient stream (covers L1-hit latency ~39cyc).
// Coef slot = m*32 + rt; pairs (j, j+2^l), j = ((m>>l)<<(l+1)) | (m & (2^l-1)).
__device__ __forceinline__ void pass5(u64* Xv, const float2* __restrict__ lt) {
    float2 cf[4];
#pragma unroll
    for (int t = 0; t < 4; ++t) cf[t] = __ldg(lt + t * 32);

#pragma unroll
    for (int u = 0; u < 20; ++u) {
        const int l = u >> 2;
        const int q = u & 3;
        float2 nf[4];
        if (u < 19) {
            const int l2 = (u + 1) >> 2;
            const int q2 = (u + 1) & 3;
#pragma unroll
            for (int t = 0; t < 4; ++t)
                nf[t] = __ldg(lt + l2 * HALF + (q2 * 4 + t) * 32);
        }
#pragma unroll
        for (int t = 0; t < 4; ++t) {
            const int m  = q * 4 + t;
            const int sg = 1 << l;
            const int j  = ((m >> l) << (l + 1)) | (m & (sg - 1));
            const u64 cc = pk2(cf[t].x);
            const u64 ss = pk2(cf[t].y);
            const u64 ns = ss ^ 0x8000000080000000ULL;
            rot(Xv[j], Xv[j + sg], cc, ss, ns);
        }
#pragma unroll
        for (int t = 0; t < 4; ++t) cf[t] = nf[t];
    }
}

// 16KB tile: 1024 rows x 2 batch-pairs (b = bp&1); phases select bh = bp>>1.
// addr(row,b) = (row*2 + b) ^ (((row>>5)&7)<<1). For the 16 active lanes
// (8 rt x 2 b) all mod-16 slots are distinct in BOTH groupings -> conflict-free.
// Folded forms (derivation in analysis; no carries into XOR bits):
#define ADRA(j) (baseA + (((j) << 1) ^ eA))                     // row = rt*32+j
#define ADRB(j) ((baseB ^ ((((j) & 7)) << 1)) + ((j) << 6))     // row = rt+32j

extern "C" __global__ void __launch_bounds__(NTHREADS, 5)
butterfly_kernel(const float* __restrict__ X, float* __restrict__ Y)
{
    extern __shared__ u64 tile[];          // 2048 u64 = 16 KB

    const int bp = threadIdx.x & 3;        // batch-pair (2 cols) 0..3
    const int bh = bp >> 1;                // exchange phase 0/1
    const int b  = bp & 1;                 // slot within tile
    const int rt = threadIdx.x >> 2;       // row-thread 0..31
    const long long bb = (long long)blockIdx.x * TB + bp * 2;

    const int eA    = (rt & 7) << 1;
    const int baseA = rt * 64 + b;
    const int baseB = rt * 2 + b;

    u64 Xa[32];                            // 32 rows x 2 batch columns

    // Load, layout A (reg j = row rt*32+j). .cg: bypass L1, keep it for coefs.
#pragma unroll
    for (int j = 0; j < 32; ++j)
        Xa[j] = __ldcg(reinterpret_cast<const u64*>(X + (long long)(rt * 32 + j) * BATCH + bb));

    const float2* lt = g_cs + rt;

    // two-phase exchanges through the 16KB tile
#define XCHG_AB() do {                                                        \
    _Pragma("unroll 1")                                                       \
    for (int ph = 0; ph < 2; ++ph) {                                          \
        __syncthreads();                                                      \
        if (bh == ph) { _Pragma("unroll")                                     \
            for (int j = 0; j < 32; ++j) tile[ADRA(j)] = Xa[j]; }             \
        __syncthreads();                                                      \
        if (bh == ph) { _Pragma("unroll")                                     \
            for (int j = 0; j < 32; ++j) Xa[j] = tile[ADRB(j)]; }             \
    } } while (0)

#define XCHG_BA() do {                                                        \
    _Pragma("unroll 1")                                                       \
    for (int ph = 0; ph < 2; ++ph) {                                          \
        __syncthreads();                                                      \
        if (bh == ph) { _Pragma("unroll")                                     \
            for (int j = 0; j < 32; ++j) tile[ADRB(j)] = Xa[j]; }             \
        __syncthreads();                                                      \
        if (bh == ph) { _Pragma("unroll")                                     \
            for (int j = 0; j < 32; ++j) Xa[j] = tile[ADRA(j)]; }             \
    } } while (0)

#pragma unroll 1
    for (int sp = 0; sp < 2; ++sp) {
        // layers sp*10 .. sp*10+4 (register strides 1..16 in layout A)
        pass5(Xa, lt + (sp * 10) * HALF);

        XCHG_AB();

        // layers sp*10+5 .. sp*10+9 (strides 32..512 in layout B)
        pass5(Xa, lt + (sp * 10 + 5) * HALF);

        if (sp == 0) XCHG_BA();
    }

    // Store, layout B (reg j = row rt+32j), .cg to bypass L1.
#pragma unroll
    for (int j = 0; j < 32; ++j)
        __stcg(reinterpret_cast<u64*>(Y + (long long)(rt + 32 * j) * BATCH + bb), Xa[j]);
}

extern "C" void kernel_launch(void* const* d_in, const int* in_sizes, int n_in,
                              void* d_out, int out_size)
{
    const float* X = (const float*)d_in[0];
    const float* A = (const float*)d_in[1];
    if (n_in >= 2 && in_sizes[0] < in_sizes[1]) {   // defensive: X is the big one
        const float* t = X; X = A; A = t;
    }
    float* Y = (float*)d_out;

    cudaFuncSetAttribute(butterfly_kernel,
                         cudaFuncAttributeMaxDynamicSharedMemorySize, 16384);

    sincos_kernel<<<(DEPTH * HALF + 255) / 256, 256>>>(A);
    butterfly_kernel<<<NBLOCKS, NTHREADS, 16384>>>(X, Y);
}